// round 2
// baseline (speedup 1.0000x reference)
#include <cuda_runtime.h>
#include <math.h>

#define Bv 8
#define Tv 1024
#define Cv 2048
#define NH 16
#define HD 128
#define M_ROWS (Bv * Tv)      /* 8192 */
#define N_QKV  (3 * Cv)       /* 6144 */

/* Scratch buffers (allocation-free rule: __device__ globals). */
__device__ float g_qkv[(size_t)M_ROWS * N_QKV];  /* [B,T,3C] */
__device__ float g_y[(size_t)M_ROWS * Cv];       /* [B,T,C]  */

/* ------------------------------------------------------------------ */
/* SGEMM: C[M,N] = A[M,K] * B[K,N] + bias[N]                          */
/* BM=BN=128, BK=8, 256 threads, 8x8 microtile                        */
/* ------------------------------------------------------------------ */
__global__ __launch_bounds__(256) void sgemm_bias(
    const float* __restrict__ A, const float* __restrict__ Bm,
    const float* __restrict__ bias, float* __restrict__ Cc,
    int M, int N, int K)
{
    const int BM = 128, BN = 128, BK = 8, TM = 8, TN = 8;
    __shared__ float As[BK][BM + 4];   /* stride 132, rows 16B aligned */
    __shared__ float Bs[BK][BN + 4];

    const int t = threadIdx.x;
    const int tx = t % (BN / TN);      /* 0..15 */
    const int ty = t / (BN / TN);      /* 0..15 */
    const int rowBase = blockIdx.y * BM;
    const int colBase = blockIdx.x * BN;

    const int aRow = t / 2;            /* 0..127 */
    const int aCol = (t % 2) * 4;      /* 0 or 4 */
    const int bRow = t / 32;           /* 0..7   */
    const int bCol = (t % 32) * 4;     /* 0..124 */

    float acc[TM][TN];
#pragma unroll
    for (int i = 0; i < TM; i++)
#pragma unroll
        for (int j = 0; j < TN; j++) acc[i][j] = 0.0f;

    const float* Aptr = A + (size_t)rowBase * K;
    const float* Bptr = Bm + colBase;

    for (int k0 = 0; k0 < K; k0 += BK) {
        float4 av = *(const float4*)(Aptr + (size_t)aRow * K + k0 + aCol);
        As[aCol + 0][aRow] = av.x;
        As[aCol + 1][aRow] = av.y;
        As[aCol + 2][aRow] = av.z;
        As[aCol + 3][aRow] = av.w;
        float4 bv = *(const float4*)(Bptr + (size_t)(k0 + bRow) * N + bCol);
        *(float4*)&Bs[bRow][bCol] = bv;
        __syncthreads();

#pragma unroll
        for (int k = 0; k < BK; k++) {
            float ra[TM], rb[TN];
            *(float4*)&ra[0] = *(const float4*)&As[k][ty * TM];
            *(float4*)&ra[4] = *(const float4*)&As[k][ty * TM + 4];
            *(float4*)&rb[0] = *(const float4*)&Bs[k][tx * TN];
            *(float4*)&rb[4] = *(const float4*)&Bs[k][tx * TN + 4];
#pragma unroll
            for (int i = 0; i < TM; i++)
#pragma unroll
                for (int j = 0; j < TN; j++)
                    acc[i][j] += ra[i] * rb[j];
        }
        __syncthreads();
    }

#pragma unroll
    for (int i = 0; i < TM; i++) {
        const int r = rowBase + ty * TM + i;
        float* crow = Cc + (size_t)r * N + colBase + tx * TN;
        const float* brow = bias + colBase + tx * TN;
#pragma unroll
        for (int j = 0; j < TN; j += 4) {
            float4 o;
            o.x = acc[i][j + 0] + brow[j + 0];
            o.y = acc[i][j + 1] + brow[j + 1];
            o.z = acc[i][j + 2] + brow[j + 2];
            o.w = acc[i][j + 3] + brow[j + 3];
            *(float4*)(crow + j) = o;
        }
    }
}

/* ------------------------------------------------------------------ */
/* Causal flash attention, fp32.                                      */
/* Per CTA: one (b, h, q-tile of 64). 256 threads.                    */
/* ------------------------------------------------------------------ */
#define QTILE 64
#define KTILE 64
#define NQT (Tv / QTILE)       /* 16 */
#define QK_STRIDE 129          /* 64x129 padded */
#define V_STRIDE 132
#define P_STRIDE 68

#define FLASH_SMEM_FLOATS (64 * QK_STRIDE * 2 + 64 * V_STRIDE + 64 * P_STRIDE + 3 * 64)
#define FLASH_SMEM_BYTES (FLASH_SMEM_FLOATS * 4)

__global__ __launch_bounds__(256) void flash_attn(
    const float* __restrict__ qkv, float* __restrict__ Y)
{
    extern __shared__ float sm[];
    float* Qs = sm;                          /* [64][129] */
    float* Ks = Qs + 64 * QK_STRIDE;         /* [64][129] */
    float* Vs = Ks + 64 * QK_STRIDE;         /* [64][132] */
    float* Ps = Vs + 64 * V_STRIDE;          /* [64][68]  */
    float* mrow = Ps + 64 * P_STRIDE;
    float* lrow = mrow + 64;
    float* frow = lrow + 64;

    const int t = threadIdx.x;
    const int blk = blockIdx.x;
    const int qt = blk % NQT;
    const int h = (blk / NQT) % NH;
    const int b = blk / (NQT * NH);

    const size_t rowStride = 3 * Cv;
    const float scale = 0.08838834764831845f;  /* 1/sqrt(128) */

    /* thread mappings */
    const int s_r0 = (t / 16) * 4;           /* S rows (4)  */
    const int s_c0 = (t % 16) * 4;           /* S cols (4)  */
    const int o_r0 = (t / 16) * 4;           /* O rows (4)  */
    const int o_c0 = (t % 16) * 8;           /* O cols (8)  */
    const int rRow = t >> 2;                 /* softmax row */
    const int seg = t & 3;                   /* 16-col segment */

    /* load Q tile [64][128] */
    const float* qbase = qkv + ((size_t)b * Tv + qt * QTILE) * rowStride + h * HD;
#pragma unroll
    for (int chunk = 0; chunk < 8; chunk++) {
        int linear = chunk * 1024 + t * 4;
        int r = linear >> 7;
        int d = linear & 127;
        float4 v = *(const float4*)(qbase + (size_t)r * rowStride + d);
        Qs[r * QK_STRIDE + d + 0] = v.x;
        Qs[r * QK_STRIDE + d + 1] = v.y;
        Qs[r * QK_STRIDE + d + 2] = v.z;
        Qs[r * QK_STRIDE + d + 3] = v.w;
    }
    if (t < 64) { mrow[t] = -3.0e38f; lrow[t] = 0.0f; }

    float acc[4][8];
#pragma unroll
    for (int i = 0; i < 4; i++)
#pragma unroll
        for (int j = 0; j < 8; j++) acc[i][j] = 0.0f;

    __syncthreads();

    for (int kt = 0; kt <= qt; kt++) {
        /* load K, V tiles */
        const float* kbase = qkv + ((size_t)b * Tv + kt * KTILE) * rowStride + Cv + h * HD;
        const float* vbase = kbase + Cv;
#pragma unroll
        for (int chunk = 0; chunk < 8; chunk++) {
            int linear = chunk * 1024 + t * 4;
            int r = linear >> 7;
            int d = linear & 127;
            float4 kv = *(const float4*)(kbase + (size_t)r * rowStride + d);
            Ks[r * QK_STRIDE + d + 0] = kv.x;
            Ks[r * QK_STRIDE + d + 1] = kv.y;
            Ks[r * QK_STRIDE + d + 2] = kv.z;
            Ks[r * QK_STRIDE + d + 3] = kv.w;
            float4 vv = *(const float4*)(vbase + (size_t)r * rowStride + d);
            *(float4*)&Vs[r * V_STRIDE + d] = vv;
        }
        __syncthreads();

        /* S = Q * K^T (4x4 microtile per thread) */
        float sreg[4][4];
#pragma unroll
        for (int i = 0; i < 4; i++)
#pragma unroll
            for (int j = 0; j < 4; j++) sreg[i][j] = 0.0f;

#pragma unroll 4
        for (int k = 0; k < 128; k++) {
            float a[4], bb[4];
#pragma unroll
            for (int i = 0; i < 4; i++) a[i] = Qs[(s_r0 + i) * QK_STRIDE + k];
#pragma unroll
            for (int j = 0; j < 4; j++) bb[j] = Ks[(s_c0 + j) * QK_STRIDE + k];
#pragma unroll
            for (int i = 0; i < 4; i++)
#pragma unroll
                for (int j = 0; j < 4; j++)
                    sreg[i][j] += a[i] * bb[j];
        }

        /* scale + causal mask + write to Ps */
        const bool diag = (kt == qt);
#pragma unroll
        for (int i = 0; i < 4; i++) {
            float4 o;
            float v0 = sreg[i][0] * scale;
            float v1 = sreg[i][1] * scale;
            float v2 = sreg[i][2] * scale;
            float v3 = sreg[i][3] * scale;
            if (diag) {
                int qr = s_r0 + i;
                if (s_c0 + 0 > qr) v0 = -1.0e30f;
                if (s_c0 + 1 > qr) v1 = -1.0e30f;
                if (s_c0 + 2 > qr) v2 = -1.0e30f;
                if (s_c0 + 3 > qr) v3 = -1.0e30f;
            }
            o.x = v0; o.y = v1; o.z = v2; o.w = v3;
            *(float4*)&Ps[(s_r0 + i) * P_STRIDE + s_c0] = o;
        }
        __syncthreads();

        /* online softmax: 4 threads per row */
        {
            float mOld = mrow[rRow];
            float lOld = lrow[rRow];
            float* prow = Ps + rRow * P_STRIDE + seg * 16;
            float lm = -3.0e38f;
#pragma unroll
            for (int c = 0; c < 16; c++) lm = fmaxf(lm, prow[c]);
            lm = fmaxf(lm, __shfl_xor_sync(0xffffffffu, lm, 1));
            lm = fmaxf(lm, __shfl_xor_sync(0xffffffffu, lm, 2));
            float mNew = fmaxf(mOld, lm);
            float lsum = 0.0f;
#pragma unroll
            for (int c = 0; c < 16; c++) {
                float p = __expf(prow[c] - mNew);
                prow[c] = p;
                lsum += p;
            }
            lsum += __shfl_xor_sync(0xffffffffu, lsum, 1);
            lsum += __shfl_xor_sync(0xffffffffu, lsum, 2);
            if (seg == 0) {
                float f = __expf(mOld - mNew);
                frow[rRow] = f;
                mrow[rRow] = mNew;
                lrow[rRow] = lOld * f + lsum;
            }
        }
        __syncthreads();

        /* rescale acc + accumulate P*V */
        {
            float f[4];
#pragma unroll
            for (int i = 0; i < 4; i++) f[i] = frow[o_r0 + i];
#pragma unroll
            for (int i = 0; i < 4; i++)
#pragma unroll
                for (int j = 0; j < 8; j++) acc[i][j] *= f[i];

#pragma unroll 2
            for (int n = 0; n < 64; n++) {
                float p[4];
#pragma unroll
                for (int i = 0; i < 4; i++) p[i] = Ps[(o_r0 + i) * P_STRIDE + n];
                float4 va = *(const float4*)&Vs[n * V_STRIDE + o_c0];
                float4 vb = *(const float4*)&Vs[n * V_STRIDE + o_c0 + 4];
#pragma unroll
                for (int i = 0; i < 4; i++) {
                    acc[i][0] += p[i] * va.x;
                    acc[i][1] += p[i] * va.y;
                    acc[i][2] += p[i] * va.z;
                    acc[i][3] += p[i] * va.w;
                    acc[i][4] += p[i] * vb.x;
                    acc[i][5] += p[i] * vb.y;
                    acc[i][6] += p[i] * vb.z;
                    acc[i][7] += p[i] * vb.w;
                }
            }
        }
        __syncthreads();
    }

    /* epilogue: normalize and write y [B,T,C] with head interleave */
    float* ybase = Y + ((size_t)b * Tv + qt * QTILE) * Cv + h * HD;
#pragma unroll
    for (int i = 0; i < 4; i++) {
        float inv = 1.0f / lrow[o_r0 + i];
        float4 o1, o2;
        o1.x = acc[i][0] * inv; o1.y = acc[i][1] * inv;
        o1.z = acc[i][2] * inv; o1.w = acc[i][3] * inv;
        o2.x = acc[i][4] * inv; o2.y = acc[i][5] * inv;
        o2.z = acc[i][6] * inv; o2.w = acc[i][7] * inv;
        *(float4*)(ybase + (size_t)(o_r0 + i) * Cv + o_c0) = o1;
        *(float4*)(ybase + (size_t)(o_r0 + i) * Cv + o_c0 + 4) = o2;
    }
}

/* ------------------------------------------------------------------ */
extern "C" void kernel_launch(void* const* d_in, const int* in_sizes, int n_in,
                              void* d_out, int out_size)
{
    (void)in_sizes; (void)n_in; (void)out_size;
    const float* x      = (const float*)d_in[0];
    const float* W_attn = (const float*)d_in[1];
    const float* b_attn = (const float*)d_in[2];
    const float* W_proj = (const float*)d_in[3];
    const float* b_proj = (const float*)d_in[4];
    float* out = (float*)d_out;

    float *qkv = nullptr, *y = nullptr;
    cudaGetSymbolAddress((void**)&qkv, g_qkv);
    cudaGetSymbolAddress((void**)&y, g_y);

    cudaFuncSetAttribute(flash_attn,
                         cudaFuncAttributeMaxDynamicSharedMemorySize,
                         FLASH_SMEM_BYTES);

    dim3 blk(256);
    /* QKV projection: [8192,2048] x [2048,6144] */
    sgemm_bias<<<dim3(N_QKV / 128, M_ROWS / 128), blk>>>(
        x, W_attn, b_attn, qkv, M_ROWS, N_QKV, Cv);

    /* causal attention */
    flash_attn<<<dim3(Bv * NH * NQT), blk, FLASH_SMEM_BYTES>>>(qkv, y);

    /* output projection: [8192,2048] x [2048,2048] */
    sgemm_bias<<<dim3(Cv / 128, M_ROWS / 128), blk>>>(
        y, W_proj, b_proj, out, M_ROWS, Cv, Cv);
}

// round 6
// speedup vs baseline: 1.8650x; 1.8650x over previous
#include <cuda_runtime.h>
#include <cuda_bf16.h>
#include <cstdint>
#include <math.h>

#define Bv 8
#define Tv 1024
#define Cv 2048
#define NH 16
#define HD 128
#define M_ROWS (Bv * Tv)      /* 8192 */
#define N_QKV  (3 * Cv)       /* 6144 */

/* ------------------------------------------------------------------ */
/* Scratch (allocation-free rule: __device__ globals)                  */
/* ------------------------------------------------------------------ */
__device__ __align__(256) float g_qkv[(size_t)M_ROWS * N_QKV];
__device__ __align__(256) float g_y[(size_t)M_ROWS * Cv];
__device__ __align__(256) __nv_bfloat16 g_xhi[(size_t)M_ROWS * Cv];
__device__ __align__(256) __nv_bfloat16 g_xlo[(size_t)M_ROWS * Cv];
__device__ __align__(256) __nv_bfloat16 g_yhi[(size_t)M_ROWS * Cv];
__device__ __align__(256) __nv_bfloat16 g_ylo[(size_t)M_ROWS * Cv];
__device__ __align__(256) __nv_bfloat16 g_wah[(size_t)N_QKV * Cv];  /* W_attn^T hi [6144][2048] */
__device__ __align__(256) __nv_bfloat16 g_wal[(size_t)N_QKV * Cv];
__device__ __align__(256) __nv_bfloat16 g_wph[(size_t)Cv * Cv];     /* W_proj^T hi [2048][2048] */
__device__ __align__(256) __nv_bfloat16 g_wpl[(size_t)Cv * Cv];

/* ------------------------------------------------------------------ */
/* Helpers (baseline PTX only — no sm_103a-gated instructions)        */
/* ------------------------------------------------------------------ */
__device__ __forceinline__ uint32_t smem_u32(const void* p) {
    uint32_t a;
    asm("{ .reg .u64 t; cvta.to.shared.u64 t, %1; cvt.u32.u64 %0, t; }" : "=r"(a) : "l"(p));
    return a;
}
__device__ __forceinline__ void cpa16(uint32_t dst, const void* src) {
    asm volatile("cp.async.cg.shared.global [%0], [%1], 16;" :: "r"(dst), "l"(src));
}
__device__ __forceinline__ void cpa_commit() {
    asm volatile("cp.async.commit_group;" ::: "memory");
}
__device__ __forceinline__ void cpa_wait0() {
    asm volatile("cp.async.wait_group 0;" ::: "memory");
}
__device__ __forceinline__ void ldm4(uint32_t* r, uint32_t a) {
    asm volatile("ldmatrix.sync.aligned.m8n8.x4.shared.b16 {%0,%1,%2,%3}, [%4];"
                 : "=r"(r[0]), "=r"(r[1]), "=r"(r[2]), "=r"(r[3]) : "r"(a));
}
__device__ __forceinline__ void mma16816(float* c, const uint32_t* a, const uint32_t* b) {
    asm volatile("mma.sync.aligned.m16n8k16.row.col.f32.bf16.bf16.f32 "
                 "{%0,%1,%2,%3}, {%4,%5,%6,%7}, {%8,%9}, {%0,%1,%2,%3};"
                 : "+f"(c[0]), "+f"(c[1]), "+f"(c[2]), "+f"(c[3])
                 : "r"(a[0]), "r"(a[1]), "r"(a[2]), "r"(a[3]), "r"(b[0]), "r"(b[1]));
}

/* ------------------------------------------------------------------ */
/* Conversion kernels                                                  */
/* ------------------------------------------------------------------ */
__global__ __launch_bounds__(256) void split_f32(
    const float* __restrict__ in, __nv_bfloat16* __restrict__ hi,
    __nv_bfloat16* __restrict__ lo, int n4)
{
    int i = blockIdx.x * blockDim.x + threadIdx.x;
    if (i >= n4) return;
    float4 v = ((const float4*)in)[i];
    __nv_bfloat16 hx = __float2bfloat16(v.x), hy = __float2bfloat16(v.y);
    __nv_bfloat16 hz = __float2bfloat16(v.z), hw = __float2bfloat16(v.w);
    float lx = v.x - __bfloat162float(hx), ly = v.y - __bfloat162float(hy);
    float lz = v.z - __bfloat162float(hz), lw = v.w - __bfloat162float(hw);
    __nv_bfloat162* hp = (__nv_bfloat162*)hi;
    __nv_bfloat162* lp = (__nv_bfloat162*)lo;
    hp[2 * i + 0] = __nv_bfloat162(hx, hy);
    hp[2 * i + 1] = __nv_bfloat162(hz, hw);
    lp[2 * i + 0] = __nv_bfloat162(__float2bfloat16(lx), __float2bfloat16(ly));
    lp[2 * i + 1] = __nv_bfloat162(__float2bfloat16(lz), __float2bfloat16(lw));
}

/* W [K][N] f32 -> Th/Tl [N][K] bf16 */
__global__ __launch_bounds__(256) void transpose_split(
    const float* __restrict__ W, __nv_bfloat16* __restrict__ Th,
    __nv_bfloat16* __restrict__ Tl, int K, int N)
{
    __shared__ float tile[32][33];
    int n0 = blockIdx.x * 32, k0 = blockIdx.y * 32;
    int tx = threadIdx.x, ty = threadIdx.y;  /* 32 x 8 */
#pragma unroll
    for (int i = 0; i < 32; i += 8)
        tile[ty + i][tx] = W[(size_t)(k0 + ty + i) * N + n0 + tx];
    __syncthreads();
#pragma unroll
    for (int i = 0; i < 32; i += 8) {
        float v = tile[tx][ty + i];
        __nv_bfloat16 h = __float2bfloat16(v);
        __nv_bfloat16 l = __float2bfloat16(v - __bfloat162float(h));
        Th[(size_t)(n0 + ty + i) * K + k0 + tx] = h;
        Tl[(size_t)(n0 + ty + i) * K + k0 + tx] = l;
    }
}

/* ------------------------------------------------------------------ */
/* Split-bf16 GEMM via mma.sync (HMMA): C = A*B + bias                 */
/* A hi/lo [M][K] bf16, Bt hi/lo [N][K] bf16 (K-major both)            */
/* CTA 128x128, BK=32, 8 warps each 64x32, cp.async double buffer      */
/* ------------------------------------------------------------------ */
#define BKC 32
#define ROWP 40                                   /* padded row, bf16 elems */
#define MAT_BYTES (128 * ROWP * 2)                /* 10240 */
#define AH_OFF 0
#define AL_OFF MAT_BYTES
#define BH_OFF (2 * MAT_BYTES)
#define BL_OFF (3 * MAT_BYTES)
#define STAGE_BYTES (4 * MAT_BYTES)               /* 40960 */
#define GEMM_SMEM_BYTES (2 * STAGE_BYTES)         /* 81920 */

__global__ __launch_bounds__(256, 1) void gemm_mma(
    const __nv_bfloat16* __restrict__ Ah, const __nv_bfloat16* __restrict__ Al,
    const __nv_bfloat16* __restrict__ Bth, const __nv_bfloat16* __restrict__ Btl,
    const float* __restrict__ bias, float* __restrict__ C, int N, int K)
{
    extern __shared__ char smem[];
    const uint32_t smem_base = smem_u32(smem);
    const int tid = threadIdx.x;
    const int warp = tid >> 5;
    const int lane = tid & 31;
    const int wm = warp >> 2;          /* 0..1  -> M offset 64*wm */
    const int wn = warp & 3;           /* 0..3  -> N offset 32*wn */
    const int rowBase = blockIdx.y * 128;
    const int colBase = blockIdx.x * 128;

    /* ldmatrix per-lane byte offsets (stage/kk-independent) */
    const int r8 = lane & 7;
    const int blk = lane >> 3;
    uint32_t offA[4], offB[2];
#pragma unroll
    for (int mt = 0; mt < 4; mt++) {
        int mrow = wm * 64 + mt * 16 + r8 + (blk & 1) * 8;
        offA[mt] = (uint32_t)((mrow * ROWP + (blk >> 1) * 8) * 2);
    }
#pragma unroll
    for (int p = 0; p < 2; p++) {
        int nrow = wn * 32 + p * 16 + (blk >> 1) * 8 + r8;
        offB[p] = (uint32_t)((nrow * ROWP + (blk & 1) * 8) * 2);
    }

    float acc[4][4][4];
#pragma unroll
    for (int mt = 0; mt < 4; mt++)
#pragma unroll
        for (int nt = 0; nt < 4; nt++)
#pragma unroll
            for (int i = 0; i < 4; i++) acc[mt][nt][i] = 0.0f;

    const int NS = K / BKC;

    /* producer: load chunk s into stage s&1 */
#define LOAD_CHUNK(s) do {                                                     \
        int _st = (s) & 1; int _k0 = (s) * BKC;                                \
        uint32_t _sb = smem_base + _st * STAGE_BYTES;                          \
        _Pragma("unroll")                                                      \
        for (int _i = 0; _i < 2; _i++) {                                       \
            int _v = tid + (_i << 8);                                          \
            int _row = _v >> 2, _c8 = (_v & 3) << 3;                           \
            uint32_t _so = (uint32_t)(_row * ROWP + _c8) * 2;                  \
            size_t _ga = (size_t)(rowBase + _row) * K + _k0 + _c8;             \
            size_t _gb = (size_t)(colBase + _row) * K + _k0 + _c8;             \
            cpa16(_sb + AH_OFF + _so, Ah + _ga);                               \
            cpa16(_sb + AL_OFF + _so, Al + _ga);                               \
            cpa16(_sb + BH_OFF + _so, Bth + _gb);                              \
            cpa16(_sb + BL_OFF + _so, Btl + _gb);                              \
        }                                                                      \
        cpa_commit();                                                          \
    } while (0)

    LOAD_CHUNK(0);

    for (int s = 0; s < NS; s++) {
        cpa_wait0();
        __syncthreads();
        if (s + 1 < NS) LOAD_CHUNK(s + 1);

        const uint32_t sb = smem_base + (s & 1) * STAGE_BYTES;
#pragma unroll
        for (int kk = 0; kk < BKC; kk += 16) {
            uint32_t ahf[4][4], alf[4][4], bhf[2][4], blf[2][4];
#pragma unroll
            for (int mt = 0; mt < 4; mt++) {
                ldm4(ahf[mt], sb + AH_OFF + offA[mt] + kk * 2);
                ldm4(alf[mt], sb + AL_OFF + offA[mt] + kk * 2);
            }
#pragma unroll
            for (int p = 0; p < 2; p++) {
                ldm4(bhf[p], sb + BH_OFF + offB[p] + kk * 2);
                ldm4(blf[p], sb + BL_OFF + offB[p] + kk * 2);
            }
#pragma unroll
            for (int mt = 0; mt < 4; mt++)
#pragma unroll
                for (int nt = 0; nt < 4; nt++) {
                    const uint32_t* bh = &bhf[nt >> 1][(nt & 1) * 2];
                    const uint32_t* bl = &blf[nt >> 1][(nt & 1) * 2];
                    mma16816(acc[mt][nt], ahf[mt], bh);
                    mma16816(acc[mt][nt], alf[mt], bh);
                    mma16816(acc[mt][nt], ahf[mt], bl);
                }
        }
        __syncthreads();
    }

    /* epilogue */
#pragma unroll
    for (int mt = 0; mt < 4; mt++) {
        int row0 = rowBase + wm * 64 + mt * 16 + (lane >> 2);
#pragma unroll
        for (int nt = 0; nt < 4; nt++) {
            int col = colBase + wn * 32 + nt * 8 + (lane & 3) * 2;
            float b0 = bias[col], b1 = bias[col + 1];
            float2 v0 = make_float2(acc[mt][nt][0] + b0, acc[mt][nt][1] + b1);
            float2 v1 = make_float2(acc[mt][nt][2] + b0, acc[mt][nt][3] + b1);
            *(float2*)(C + (size_t)row0 * N + col) = v0;
            *(float2*)(C + (size_t)(row0 + 8) * N + col) = v1;
        }
    }
#undef LOAD_CHUNK
}

/* ------------------------------------------------------------------ */
/* Causal flash attention, fp32 (unchanged, known-correct)             */
/* ------------------------------------------------------------------ */
#define QTILE 64
#define KTILE 64
#define NQT (Tv / QTILE)
#define QK_STRIDE 129
#define V_STRIDE 132
#define P_STRIDE 68
#define FLASH_SMEM_FLOATS (64 * QK_STRIDE * 2 + 64 * V_STRIDE + 64 * P_STRIDE + 3 * 64)
#define FLASH_SMEM_BYTES (FLASH_SMEM_FLOATS * 4)

__global__ __launch_bounds__(256) void flash_attn(
    const float* __restrict__ qkv, float* __restrict__ Y)
{
    extern __shared__ float sm[];
    float* Qs = sm;
    float* Ks = Qs + 64 * QK_STRIDE;
    float* Vs = Ks + 64 * QK_STRIDE;
    float* Ps = Vs + 64 * V_STRIDE;
    float* mrow = Ps + 64 * P_STRIDE;
    float* lrow = mrow + 64;
    float* frow = lrow + 64;

    const int t = threadIdx.x;
    const int blk = blockIdx.x;
    const int qt = blk % NQT;
    const int h = (blk / NQT) % NH;
    const int b = blk / (NQT * NH);

    const size_t rowStride = 3 * Cv;
    const float scale = 0.08838834764831845f;

    const int s_r0 = (t / 16) * 4;
    const int s_c0 = (t % 16) * 4;
    const int o_r0 = (t / 16) * 4;
    const int o_c0 = (t % 16) * 8;
    const int rRow = t >> 2;
    const int seg = t & 3;

    const float* qbase = qkv + ((size_t)b * Tv + qt * QTILE) * rowStride + h * HD;
#pragma unroll
    for (int chunk = 0; chunk < 8; chunk++) {
        int linear = chunk * 1024 + t * 4;
        int r = linear >> 7;
        int d = linear & 127;
        float4 v = *(const float4*)(qbase + (size_t)r * rowStride + d);
        Qs[r * QK_STRIDE + d + 0] = v.x;
        Qs[r * QK_STRIDE + d + 1] = v.y;
        Qs[r * QK_STRIDE + d + 2] = v.z;
        Qs[r * QK_STRIDE + d + 3] = v.w;
    }
    if (t < 64) { mrow[t] = -3.0e38f; lrow[t] = 0.0f; }

    float acc[4][8];
#pragma unroll
    for (int i = 0; i < 4; i++)
#pragma unroll
        for (int j = 0; j < 8; j++) acc[i][j] = 0.0f;

    __syncthreads();

    for (int kt = 0; kt <= qt; kt++) {
        const float* kbase = qkv + ((size_t)b * Tv + kt * KTILE) * rowStride + Cv + h * HD;
        const float* vbase = kbase + Cv;
#pragma unroll
        for (int chunk = 0; chunk < 8; chunk++) {
            int linear = chunk * 1024 + t * 4;
            int r = linear >> 7;
            int d = linear & 127;
            float4 kv = *(const float4*)(kbase + (size_t)r * rowStride + d);
            Ks[r * QK_STRIDE + d + 0] = kv.x;
            Ks[r * QK_STRIDE + d + 1] = kv.y;
            Ks[r * QK_STRIDE + d + 2] = kv.z;
            Ks[r * QK_STRIDE + d + 3] = kv.w;
            float4 vv = *(const float4*)(vbase + (size_t)r * rowStride + d);
            *(float4*)&Vs[r * V_STRIDE + d] = vv;
        }
        __syncthreads();

        float sreg[4][4];
#pragma unroll
        for (int i = 0; i < 4; i++)
#pragma unroll
            for (int j = 0; j < 4; j++) sreg[i][j] = 0.0f;

#pragma unroll 4
        for (int k = 0; k < 128; k++) {
            float a[4], bb[4];
#pragma unroll
            for (int i = 0; i < 4; i++) a[i] = Qs[(s_r0 + i) * QK_STRIDE + k];
#pragma unroll
            for (int j = 0; j < 4; j++) bb[j] = Ks[(s_c0 + j) * QK_STRIDE + k];
#pragma unroll
            for (int i = 0; i < 4; i++)
#pragma unroll
                for (int j = 0; j < 4; j++)
                    sreg[i][j] += a[i] * bb[j];
        }

        const bool diag = (kt == qt);
#pragma unroll
        for (int i = 0; i < 4; i++) {
            float4 o;
            float v0 = sreg[i][0] * scale;
            float v1 = sreg[i][1] * scale;
            float v2 = sreg[i][2] * scale;
            float v3 = sreg[i][3] * scale;
            if (diag) {
                int qr = s_r0 + i;
                if (s_c0 + 0 > qr) v0 = -1.0e30f;
                if (s_c0 + 1 > qr) v1 = -1.0e30f;
                if (s_c0 + 2 > qr) v2 = -1.0e30f;
                if (s_c0 + 3 > qr) v3 = -1.0e30f;
            }
            o.x = v0; o.y = v1; o.z = v2; o.w = v3;
            *(float4*)&Ps[(s_r0 + i) * P_STRIDE + s_c0] = o;
        }
        __syncthreads();

        {
            float mOld = mrow[rRow];
            float lOld = lrow[rRow];
            float* prow = Ps + rRow * P_STRIDE + seg * 16;
            float lm = -3.0e38f;
#pragma unroll
            for (int c = 0; c < 16; c++) lm = fmaxf(lm, prow[c]);
            lm = fmaxf(lm, __shfl_xor_sync(0xffffffffu, lm, 1));
            lm = fmaxf(lm, __shfl_xor_sync(0xffffffffu, lm, 2));
            float mNew = fmaxf(mOld, lm);
            float lsum = 0.0f;
#pragma unroll
            for (int c = 0; c < 16; c++) {
                float p = __expf(prow[c] - mNew);
                prow[c] = p;
                lsum += p;
            }
            lsum += __shfl_xor_sync(0xffffffffu, lsum, 1);
            lsum += __shfl_xor_sync(0xffffffffu, lsum, 2);
            if (seg == 0) {
                float f = __expf(mOld - mNew);
                frow[rRow] = f;
                mrow[rRow] = mNew;
                lrow[rRow] = lOld * f + lsum;
            }
        }
        __syncthreads();

        {
            float f[4];
#pragma unroll
            for (int i = 0; i < 4; i++) f[i] = frow[o_r0 + i];
#pragma unroll
            for (int i = 0; i < 4; i++)
#pragma unroll
                for (int j = 0; j < 8; j++) acc[i][j] *= f[i];

#pragma unroll 2
            for (int n = 0; n < 64; n++) {
                float p[4];
#pragma unroll
                for (int i = 0; i < 4; i++) p[i] = Ps[(o_r0 + i) * P_STRIDE + n];
                float4 va = *(const float4*)&Vs[n * V_STRIDE + o_c0];
                float4 vb = *(const float4*)&Vs[n * V_STRIDE + o_c0 + 4];
#pragma unroll
                for (int i = 0; i < 4; i++) {
                    acc[i][0] += p[i] * va.x;
                    acc[i][1] += p[i] * va.y;
                    acc[i][2] += p[i] * va.z;
                    acc[i][3] += p[i] * va.w;
                    acc[i][4] += p[i] * vb.x;
                    acc[i][5] += p[i] * vb.y;
                    acc[i][6] += p[i] * vb.z;
                    acc[i][7] += p[i] * vb.w;
                }
            }
        }
        __syncthreads();
    }

    float* ybase = Y + ((size_t)b * Tv + qt * QTILE) * Cv + h * HD;
#pragma unroll
    for (int i = 0; i < 4; i++) {
        float inv = 1.0f / lrow[o_r0 + i];
        float4 o1, o2;
        o1.x = acc[i][0] * inv; o1.y = acc[i][1] * inv;
        o1.z = acc[i][2] * inv; o1.w = acc[i][3] * inv;
        o2.x = acc[i][4] * inv; o2.y = acc[i][5] * inv;
        o2.z = acc[i][6] * inv; o2.w = acc[i][7] * inv;
        *(float4*)(ybase + (size_t)(o_r0 + i) * Cv + o_c0) = o1;
        *(float4*)(ybase + (size_t)(o_r0 + i) * Cv + o_c0 + 4) = o2;
    }
}

/* ------------------------------------------------------------------ */
extern "C" void kernel_launch(void* const* d_in, const int* in_sizes, int n_in,
                              void* d_out, int out_size)
{
    (void)in_sizes; (void)n_in; (void)out_size;
    const float* x      = (const float*)d_in[0];
    const float* W_attn = (const float*)d_in[1];
    const float* b_attn = (const float*)d_in[2];
    const float* W_proj = (const float*)d_in[3];
    const float* b_proj = (const float*)d_in[4];
    float* out = (float*)d_out;

    float *qkv, *y;
    __nv_bfloat16 *xhi, *xlo, *yhi, *ylo, *wah, *wal, *wph, *wpl;
    cudaGetSymbolAddress((void**)&qkv, g_qkv);
    cudaGetSymbolAddress((void**)&y, g_y);
    cudaGetSymbolAddress((void**)&xhi, g_xhi);
    cudaGetSymbolAddress((void**)&xlo, g_xlo);
    cudaGetSymbolAddress((void**)&yhi, g_yhi);
    cudaGetSymbolAddress((void**)&ylo, g_ylo);
    cudaGetSymbolAddress((void**)&wah, g_wah);
    cudaGetSymbolAddress((void**)&wal, g_wal);
    cudaGetSymbolAddress((void**)&wph, g_wph);
    cudaGetSymbolAddress((void**)&wpl, g_wpl);

    cudaFuncSetAttribute(gemm_mma, cudaFuncAttributeMaxDynamicSharedMemorySize, GEMM_SMEM_BYTES);
    cudaFuncSetAttribute(flash_attn, cudaFuncAttributeMaxDynamicSharedMemorySize, FLASH_SMEM_BYTES);

    const int n4x = (M_ROWS * Cv) / 4;
    split_f32<<<(n4x + 255) / 256, 256>>>(x, xhi, xlo, n4x);
    transpose_split<<<dim3(N_QKV / 32, Cv / 32), dim3(32, 8)>>>(W_attn, wah, wal, Cv, N_QKV);
    transpose_split<<<dim3(Cv / 32, Cv / 32), dim3(32, 8)>>>(W_proj, wph, wpl, Cv, Cv);

    gemm_mma<<<dim3(N_QKV / 128, M_ROWS / 128), 256, GEMM_SMEM_BYTES>>>(
        xhi, xlo, wah, wal, b_attn, qkv, N_QKV, Cv);

    flash_attn<<<dim3(Bv * NH * NQT), 256, FLASH_SMEM_BYTES>>>(qkv, y);

    split_f32<<<(n4x + 255) / 256, 256>>>(y, yhi, ylo, n4x);
    gemm_mma<<<dim3(Cv / 128, M_ROWS / 128), 256, GEMM_SMEM_BYTES>>>(
        yhi, ylo, wph, wpl, b_proj, out, Cv, Cv);
}

// round 9
// speedup vs baseline: 2.2164x; 1.1884x over previous
#include <cuda_runtime.h>
#include <cuda_fp16.h>
#include <cuda_bf16.h>
#include <cstdint>
#include <math.h>

#define Bv 8
#define Tv 1024
#define Cv 2048
#define NH 16
#define HD 128
#define M_ROWS (Bv * Tv)      /* 8192 */
#define N_QKV  (3 * Cv)       /* 6144 */

/* ------------------------------------------------------------------ */
/* Scratch (allocation-free rule: __device__ globals)                  */
/* ------------------------------------------------------------------ */
__device__ __align__(256) float g_qkv[(size_t)M_ROWS * N_QKV];
__device__ __align__(256) float g_y[(size_t)M_ROWS * Cv];
__device__ __align__(256) __half g_xh[(size_t)M_ROWS * Cv];
__device__ __align__(256) __half g_yh[(size_t)M_ROWS * Cv];
__device__ __align__(256) __half g_wah[(size_t)N_QKV * Cv];   /* W_attn^T hi  [6144][2048] */
__device__ __align__(256) __half g_wal[(size_t)N_QKV * Cv];   /* W_attn^T res*256 */
__device__ __align__(256) __half g_wph[(size_t)Cv * Cv];      /* W_proj^T hi  [2048][2048] */
__device__ __align__(256) __half g_wpl[(size_t)Cv * Cv];      /* W_proj^T res*256 */

/* ------------------------------------------------------------------ */
/* Helpers (baseline PTX only — no sm_103a-gated instructions)        */
/* ------------------------------------------------------------------ */
__device__ __forceinline__ uint32_t smem_u32(const void* p) {
    uint32_t a;
    asm("{ .reg .u64 t; cvta.to.shared.u64 t, %1; cvt.u32.u64 %0, t; }" : "=r"(a) : "l"(p));
    return a;
}
__device__ __forceinline__ void cpa16(uint32_t dst, const void* src) {
    asm volatile("cp.async.cg.shared.global [%0], [%1], 16;" :: "r"(dst), "l"(src));
}
__device__ __forceinline__ void cpa_commit() {
    asm volatile("cp.async.commit_group;" ::: "memory");
}
__device__ __forceinline__ void cpa_wait0() {
    asm volatile("cp.async.wait_group 0;" ::: "memory");
}
__device__ __forceinline__ void ldm4(uint32_t* r, uint32_t a) {
    asm volatile("ldmatrix.sync.aligned.m8n8.x4.shared.b16 {%0,%1,%2,%3}, [%4];"
                 : "=r"(r[0]), "=r"(r[1]), "=r"(r[2]), "=r"(r[3]) : "r"(a));
}
__device__ __forceinline__ void mma16816h(float* c, const uint32_t* a, const uint32_t* b) {
    asm volatile("mma.sync.aligned.m16n8k16.row.col.f32.f16.f16.f32 "
                 "{%0,%1,%2,%3}, {%4,%5,%6,%7}, {%8,%9}, {%0,%1,%2,%3};"
                 : "+f"(c[0]), "+f"(c[1]), "+f"(c[2]), "+f"(c[3])
                 : "r"(a[0]), "r"(a[1]), "r"(a[2]), "r"(a[3]), "r"(b[0]), "r"(b[1]));
}
/* exact scale by 2^-8 on packed half2 */
__device__ __forceinline__ uint32_t hscale8(uint32_t a) {
    __half2 v = *(__half2*)&a;
    __half2 s = __floats2half2_rn(0.00390625f, 0.00390625f);
    __half2 r = __hmul2(v, s);
    return *(uint32_t*)&r;
}

/* ------------------------------------------------------------------ */
/* Conversion kernels                                                  */
/* ------------------------------------------------------------------ */
__global__ __launch_bounds__(256) void to_f16(
    const float* __restrict__ in, __half* __restrict__ out, int n4)
{
    int i = blockIdx.x * blockDim.x + threadIdx.x;
    if (i >= n4) return;
    float4 v = ((const float4*)in)[i];
    __half2* op = (__half2*)out;
    op[2 * i + 0] = __floats2half2_rn(v.x, v.y);
    op[2 * i + 1] = __floats2half2_rn(v.z, v.w);
}

/* W [K][N] f32 -> Th (fp16) and Tls (fp16, (W-Th)*256), both [N][K] */
__global__ __launch_bounds__(256) void transpose_split_f16(
    const float* __restrict__ W, __half* __restrict__ Th,
    __half* __restrict__ Tls, int K, int N)
{
    __shared__ float tile[32][33];
    int n0 = blockIdx.x * 32, k0 = blockIdx.y * 32;
    int tx = threadIdx.x, ty = threadIdx.y;  /* 32 x 8 */
#pragma unroll
    for (int i = 0; i < 32; i += 8)
        tile[ty + i][tx] = W[(size_t)(k0 + ty + i) * N + n0 + tx];
    __syncthreads();
#pragma unroll
    for (int i = 0; i < 32; i += 8) {
        float v = tile[tx][ty + i];
        __half h = __float2half_rn(v);
        float r = (v - __half2float(h)) * 256.0f;
        Th[(size_t)(n0 + ty + i) * K + k0 + tx] = h;
        Tls[(size_t)(n0 + ty + i) * K + k0 + tx] = __float2half_rn(r);
    }
}

/* ------------------------------------------------------------------ */
/* fp16 2-term GEMM via mma.sync: C = A*B + bias                       */
/*   C = Ah*Bh + (Ah*2^-8)*((B-Bh)*2^8)                                */
/* A [M][K] fp16, Bh/Bls [N][K] fp16 (K-major)                         */
/* CTA 128x128, BK=32, 8 warps each 64x32, cp.async double buffer      */
/* ------------------------------------------------------------------ */
#define BKC 32
#define ROWP 40                                   /* padded row, f16 elems */
#define MAT_BYTES (128 * ROWP * 2)                /* 10240 */
#define AH_OFF 0
#define BH_OFF MAT_BYTES
#define BL_OFF (2 * MAT_BYTES)
#define STAGE_BYTES (3 * MAT_BYTES)               /* 30720 */
#define GEMM_SMEM_BYTES (2 * STAGE_BYTES)         /* 61440 */

__global__ __launch_bounds__(256, 1) void gemm_mma(
    const __half* __restrict__ Ah,
    const __half* __restrict__ Bth, const __half* __restrict__ Btl,
    const float* __restrict__ bias, float* __restrict__ C, int N, int K)
{
    extern __shared__ char smem[];
    const uint32_t smem_base = smem_u32(smem);
    const int tid = threadIdx.x;
    const int warp = tid >> 5;
    const int lane = tid & 31;
    const int wm = warp >> 2;          /* 0..1  -> M offset 64*wm */
    const int wn = warp & 3;           /* 0..3  -> N offset 32*wn */
    const int rowBase = blockIdx.y * 128;
    const int colBase = blockIdx.x * 128;

    /* ldmatrix per-lane byte offsets (stage/kk-independent) */
    const int r8 = lane & 7;
    const int blk = lane >> 3;
    uint32_t offA[4], offB[2];
#pragma unroll
    for (int mt = 0; mt < 4; mt++) {
        int mrow = wm * 64 + mt * 16 + r8 + (blk & 1) * 8;
        offA[mt] = (uint32_t)((mrow * ROWP + (blk >> 1) * 8) * 2);
    }
#pragma unroll
    for (int p = 0; p < 2; p++) {
        int nrow = wn * 32 + p * 16 + (blk >> 1) * 8 + r8;
        offB[p] = (uint32_t)((nrow * ROWP + (blk & 1) * 8) * 2);
    }

    float acc[4][4][4];
#pragma unroll
    for (int mt = 0; mt < 4; mt++)
#pragma unroll
        for (int nt = 0; nt < 4; nt++)
#pragma unroll
            for (int i = 0; i < 4; i++) acc[mt][nt][i] = 0.0f;

    const int NS = K / BKC;

    /* producer: load chunk s into stage s&1 (3 matrices) */
#define LOAD_CHUNK(s) do {                                                     \
        int _st = (s) & 1; int _k0 = (s) * BKC;                                \
        uint32_t _sb = smem_base + _st * STAGE_BYTES;                          \
        _Pragma("unroll")                                                      \
        for (int _i = 0; _i < 2; _i++) {                                       \
            int _v = tid + (_i << 8);                                          \
            int _row = _v >> 2, _c8 = (_v & 3) << 3;                           \
            uint32_t _so = (uint32_t)(_row * ROWP + _c8) * 2;                  \
            size_t _ga = (size_t)(rowBase + _row) * K + _k0 + _c8;             \
            size_t _gb = (size_t)(colBase + _row) * K + _k0 + _c8;             \
            cpa16(_sb + AH_OFF + _so, Ah + _ga);                               \
            cpa16(_sb + BH_OFF + _so, Bth + _gb);                              \
            cpa16(_sb + BL_OFF + _so, Btl + _gb);                              \
        }                                                                      \
        cpa_commit();                                                          \
    } while (0)

    LOAD_CHUNK(0);

    for (int s = 0; s < NS; s++) {
        cpa_wait0();
        __syncthreads();
        if (s + 1 < NS) LOAD_CHUNK(s + 1);

        const uint32_t sb = smem_base + (s & 1) * STAGE_BYTES;
#pragma unroll
        for (int kk = 0; kk < BKC; kk += 16) {
            uint32_t ahf[4][4], asf[4][4], bhf[2][4], blf[2][4];
#pragma unroll
            for (int mt = 0; mt < 4; mt++)
                ldm4(ahf[mt], sb + AH_OFF + offA[mt] + kk * 2);
#pragma unroll
            for (int p = 0; p < 2; p++) {
                ldm4(bhf[p], sb + BH_OFF + offB[p] + kk * 2);
                ldm4(blf[p], sb + BL_OFF + offB[p] + kk * 2);
            }
#pragma unroll
            for (int mt = 0; mt < 4; mt++)
#pragma unroll
                for (int i = 0; i < 4; i++)
                    asf[mt][i] = hscale8(ahf[mt][i]);
#pragma unroll
            for (int mt = 0; mt < 4; mt++)
#pragma unroll
                for (int nt = 0; nt < 4; nt++) {
                    const uint32_t* bh = &bhf[nt >> 1][(nt & 1) * 2];
                    const uint32_t* bl = &blf[nt >> 1][(nt & 1) * 2];
                    mma16816h(acc[mt][nt], ahf[mt], bh);
                    mma16816h(acc[mt][nt], asf[mt], bl);
                }
        }
        __syncthreads();
    }

    /* epilogue */
#pragma unroll
    for (int mt = 0; mt < 4; mt++) {
        int row0 = rowBase + wm * 64 + mt * 16 + (lane >> 2);
#pragma unroll
        for (int nt = 0; nt < 4; nt++) {
            int col = colBase + wn * 32 + nt * 8 + (lane & 3) * 2;
            float b0 = bias[col], b1 = bias[col + 1];
            float2 v0 = make_float2(acc[mt][nt][0] + b0, acc[mt][nt][1] + b1);
            float2 v1 = make_float2(acc[mt][nt][2] + b0, acc[mt][nt][3] + b1);
            *(float2*)(C + (size_t)row0 * N + col) = v0;
            *(float2*)(C + (size_t)(row0 + 8) * N + col) = v1;
        }
    }
#undef LOAD_CHUNK
}

/* ------------------------------------------------------------------ */
/* Causal flash attention, fp32 (unchanged, known-correct)             */
/* ------------------------------------------------------------------ */
#define QTILE 64
#define KTILE 64
#define NQT (Tv / QTILE)
#define QK_STRIDE 129
#define V_STRIDE 132
#define P_STRIDE 68
#define FLASH_SMEM_FLOATS (64 * QK_STRIDE * 2 + 64 * V_STRIDE + 64 * P_STRIDE + 3 * 64)
#define FLASH_SMEM_BYTES (FLASH_SMEM_FLOATS * 4)

__global__ __launch_bounds__(256) void flash_attn(
    const float* __restrict__ qkv, float* __restrict__ Y)
{
    extern __shared__ float sm[];
    float* Qs = sm;
    float* Ks = Qs + 64 * QK_STRIDE;
    float* Vs = Ks + 64 * QK_STRIDE;
    float* Ps = Vs + 64 * V_STRIDE;
    float* mrow = Ps + 64 * P_STRIDE;
    float* lrow = mrow + 64;
    float* frow = lrow + 64;

    const int t = threadIdx.x;
    const int blk = blockIdx.x;
    const int qt = blk % NQT;
    const int h = (blk / NQT) % NH;
    const int b = blk / (NQT * NH);

    const size_t rowStride = 3 * Cv;
    const float scale = 0.08838834764831845f;

    const int s_r0 = (t / 16) * 4;
    const int s_c0 = (t % 16) * 4;
    const int o_r0 = (t / 16) * 4;
    const int o_c0 = (t % 16) * 8;
    const int rRow = t >> 2;
    const int seg = t & 3;

    const float* qbase = qkv + ((size_t)b * Tv + qt * QTILE) * rowStride + h * HD;
#pragma unroll
    for (int chunk = 0; chunk < 8; chunk++) {
        int linear = chunk * 1024 + t * 4;
        int r = linear >> 7;
        int d = linear & 127;
        float4 v = *(const float4*)(qbase + (size_t)r * rowStride + d);
        Qs[r * QK_STRIDE + d + 0] = v.x;
        Qs[r * QK_STRIDE + d + 1] = v.y;
        Qs[r * QK_STRIDE + d + 2] = v.z;
        Qs[r * QK_STRIDE + d + 3] = v.w;
    }
    if (t < 64) { mrow[t] = -3.0e38f; lrow[t] = 0.0f; }

    float acc[4][8];
#pragma unroll
    for (int i = 0; i < 4; i++)
#pragma unroll
        for (int j = 0; j < 8; j++) acc[i][j] = 0.0f;

    __syncthreads();

    for (int kt = 0; kt <= qt; kt++) {
        const float* kbase = qkv + ((size_t)b * Tv + kt * KTILE) * rowStride + Cv + h * HD;
        const float* vbase = kbase + Cv;
#pragma unroll
        for (int chunk = 0; chunk < 8; chunk++) {
            int linear = chunk * 1024 + t * 4;
            int r = linear >> 7;
            int d = linear & 127;
            float4 kv = *(const float4*)(kbase + (size_t)r * rowStride + d);
            Ks[r * QK_STRIDE + d + 0] = kv.x;
            Ks[r * QK_STRIDE + d + 1] = kv.y;
            Ks[r * QK_STRIDE + d + 2] = kv.z;
            Ks[r * QK_STRIDE + d + 3] = kv.w;
            float4 vv = *(const float4*)(vbase + (size_t)r * rowStride + d);
            *(float4*)&Vs[r * V_STRIDE + d] = vv;
        }
        __syncthreads();

        float sreg[4][4];
#pragma unroll
        for (int i = 0; i < 4; i++)
#pragma unroll
            for (int j = 0; j < 4; j++) sreg[i][j] = 0.0f;

#pragma unroll 4
        for (int k = 0; k < 128; k++) {
            float a[4], bb[4];
#pragma unroll
            for (int i = 0; i < 4; i++) a[i] = Qs[(s_r0 + i) * QK_STRIDE + k];
#pragma unroll
            for (int j = 0; j < 4; j++) bb[j] = Ks[(s_c0 + j) * QK_STRIDE + k];
#pragma unroll
            for (int i = 0; i < 4; i++)
#pragma unroll
                for (int j = 0; j < 4; j++)
                    sreg[i][j] += a[i] * bb[j];
        }

        const bool diag = (kt == qt);
#pragma unroll
        for (int i = 0; i < 4; i++) {
            float4 o;
            float v0 = sreg[i][0] * scale;
            float v1 = sreg[i][1] * scale;
            float v2 = sreg[i][2] * scale;
            float v3 = sreg[i][3] * scale;
            if (diag) {
                int qr = s_r0 + i;
                if (s_c0 + 0 > qr) v0 = -1.0e30f;
                if (s_c0 + 1 > qr) v1 = -1.0e30f;
                if (s_c0 + 2 > qr) v2 = -1.0e30f;
                if (s_c0 + 3 > qr) v3 = -1.0e30f;
            }
            o.x = v0; o.y = v1; o.z = v2; o.w = v3;
            *(float4*)&Ps[(s_r0 + i) * P_STRIDE + s_c0] = o;
        }
        __syncthreads();

        {
            float mOld = mrow[rRow];
            float lOld = lrow[rRow];
            float* prow = Ps + rRow * P_STRIDE + seg * 16;
            float lm = -3.0e38f;
#pragma unroll
            for (int c = 0; c < 16; c++) lm = fmaxf(lm, prow[c]);
            lm = fmaxf(lm, __shfl_xor_sync(0xffffffffu, lm, 1));
            lm = fmaxf(lm, __shfl_xor_sync(0xffffffffu, lm, 2));
            float mNew = fmaxf(mOld, lm);
            float lsum = 0.0f;
#pragma unroll
            for (int c = 0; c < 16; c++) {
                float p = __expf(prow[c] - mNew);
                prow[c] = p;
                lsum += p;
            }
            lsum += __shfl_xor_sync(0xffffffffu, lsum, 1);
            lsum += __shfl_xor_sync(0xffffffffu, lsum, 2);
            if (seg == 0) {
                float f = __expf(mOld - mNew);
                frow[rRow] = f;
                mrow[rRow] = mNew;
                lrow[rRow] = lOld * f + lsum;
            }
        }
        __syncthreads();

        {
            float f[4];
#pragma unroll
            for (int i = 0; i < 4; i++) f[i] = frow[o_r0 + i];
#pragma unroll
            for (int i = 0; i < 4; i++)
#pragma unroll
                for (int j = 0; j < 8; j++) acc[i][j] *= f[i];

#pragma unroll 2
            for (int n = 0; n < 64; n++) {
                float p[4];
#pragma unroll
                for (int i = 0; i < 4; i++) p[i] = Ps[(o_r0 + i) * P_STRIDE + n];
                float4 va = *(const float4*)&Vs[n * V_STRIDE + o_c0];
                float4 vb = *(const float4*)&Vs[n * V_STRIDE + o_c0 + 4];
#pragma unroll
                for (int i = 0; i < 4; i++) {
                    acc[i][0] += p[i] * va.x;
                    acc[i][1] += p[i] * va.y;
                    acc[i][2] += p[i] * va.z;
                    acc[i][3] += p[i] * va.w;
                    acc[i][4] += p[i] * vb.x;
                    acc[i][5] += p[i] * vb.y;
                    acc[i][6] += p[i] * vb.z;
                    acc[i][7] += p[i] * vb.w;
                }
            }
        }
        __syncthreads();
    }

    float* ybase = Y + ((size_t)b * Tv + qt * QTILE) * Cv + h * HD;
#pragma unroll
    for (int i = 0; i < 4; i++) {
        float inv = 1.0f / lrow[o_r0 + i];
        float4 o1, o2;
        o1.x = acc[i][0] * inv; o1.y = acc[i][1] * inv;
        o1.z = acc[i][2] * inv; o1.w = acc[i][3] * inv;
        o2.x = acc[i][4] * inv; o2.y = acc[i][5] * inv;
        o2.z = acc[i][6] * inv; o2.w = acc[i][7] * inv;
        *(float4*)(ybase + (size_t)(o_r0 + i) * Cv + o_c0) = o1;
        *(float4*)(ybase + (size_t)(o_r0 + i) * Cv + o_c0 + 4) = o2;
    }
}

/* ------------------------------------------------------------------ */
extern "C" void kernel_launch(void* const* d_in, const int* in_sizes, int n_in,
                              void* d_out, int out_size)
{
    (void)in_sizes; (void)n_in; (void)out_size;
    const float* x      = (const float*)d_in[0];
    const float* W_attn = (const float*)d_in[1];
    const float* b_attn = (const float*)d_in[2];
    const float* W_proj = (const float*)d_in[3];
    const float* b_proj = (const float*)d_in[4];
    float* out = (float*)d_out;

    float *qkv, *y;
    __half *xh, *yh, *wah, *wal, *wph, *wpl;
    cudaGetSymbolAddress((void**)&qkv, g_qkv);
    cudaGetSymbolAddress((void**)&y, g_y);
    cudaGetSymbolAddress((void**)&xh, g_xh);
    cudaGetSymbolAddress((void**)&yh, g_yh);
    cudaGetSymbolAddress((void**)&wah, g_wah);
    cudaGetSymbolAddress((void**)&wal, g_wal);
    cudaGetSymbolAddress((void**)&wph, g_wph);
    cudaGetSymbolAddress((void**)&wpl, g_wpl);

    cudaFuncSetAttribute(gemm_mma, cudaFuncAttributeMaxDynamicSharedMemorySize, GEMM_SMEM_BYTES);
    cudaFuncSetAttribute(flash_attn, cudaFuncAttributeMaxDynamicSharedMemorySize, FLASH_SMEM_BYTES);

    const int n4x = (M_ROWS * Cv) / 4;
    to_f16<<<(n4x + 255) / 256, 256>>>(x, xh, n4x);
    transpose_split_f16<<<dim3(N_QKV / 32, Cv / 32), dim3(32, 8)>>>(W_attn, wah, wal, Cv, N_QKV);
    transpose_split_f16<<<dim3(Cv / 32, Cv / 32), dim3(32, 8)>>>(W_proj, wph, wpl, Cv, Cv);

    gemm_mma<<<dim3(N_QKV / 128, M_ROWS / 128), 256, GEMM_SMEM_BYTES>>>(
        xh, wah, wal, b_attn, qkv, N_QKV, Cv);

    flash_attn<<<dim3(Bv * NH * NQT), 256, FLASH_SMEM_BYTES>>>(qkv, y);

    to_f16<<<(n4x + 255) / 256, 256>>>(y, yh, n4x);
    gemm_mma<<<dim3(Cv / 128, M_ROWS / 128), 256, GEMM_SMEM_BYTES>>>(
        yh, wph, wpl, b_proj, out, Cv, Cv);
}

// round 12
// speedup vs baseline: 2.5026x; 1.1291x over previous
#include <cuda_runtime.h>
#include <cuda_fp16.h>
#include <cuda_bf16.h>
#include <cstdint>
#include <math.h>

#define Bv 8
#define Tv 1024
#define Cv 2048
#define NH 16
#define HD 128
#define M_ROWS (Bv * Tv)      /* 8192 */
#define N_QKV  (3 * Cv)       /* 6144 */

/* ------------------------------------------------------------------ */
/* Scratch (allocation-free rule: __device__ globals)                  */
/* ------------------------------------------------------------------ */
__device__ __align__(256) float g_qkv[(size_t)M_ROWS * N_QKV];
__device__ __align__(256) float g_y[(size_t)M_ROWS * Cv];
__device__ __align__(256) __half g_xh[(size_t)M_ROWS * Cv];
__device__ __align__(256) __half g_yh[(size_t)M_ROWS * Cv];
__device__ __align__(256) __half g_wah[(size_t)N_QKV * Cv];   /* W_attn^T hi  [6144][2048] */
__device__ __align__(256) __half g_wal[(size_t)N_QKV * Cv];   /* W_attn^T res*256 */
__device__ __align__(256) __half g_wph[(size_t)Cv * Cv];      /* W_proj^T hi  [2048][2048] */
__device__ __align__(256) __half g_wpl[(size_t)Cv * Cv];      /* W_proj^T res*256 */

/* ------------------------------------------------------------------ */
/* Helpers (baseline PTX only — no sm_103a-gated instructions)        */
/* ------------------------------------------------------------------ */
__device__ __forceinline__ uint32_t smem_u32(const void* p) {
    uint32_t a;
    asm("{ .reg .u64 t; cvta.to.shared.u64 t, %1; cvt.u32.u64 %0, t; }" : "=r"(a) : "l"(p));
    return a;
}
__device__ __forceinline__ void cpa16(uint32_t dst, const void* src) {
    asm volatile("cp.async.cg.shared.global [%0], [%1], 16;" :: "r"(dst), "l"(src));
}
__device__ __forceinline__ void cpa_commit() {
    asm volatile("cp.async.commit_group;" ::: "memory");
}
__device__ __forceinline__ void cpa_wait0() {
    asm volatile("cp.async.wait_group 0;" ::: "memory");
}
__device__ __forceinline__ void cpa_wait1() {
    asm volatile("cp.async.wait_group 1;" ::: "memory");
}
__device__ __forceinline__ void ldm4(uint32_t* r, uint32_t a) {
    asm volatile("ldmatrix.sync.aligned.m8n8.x4.shared.b16 {%0,%1,%2,%3}, [%4];"
                 : "=r"(r[0]), "=r"(r[1]), "=r"(r[2]), "=r"(r[3]) : "r"(a));
}
__device__ __forceinline__ void mma16816h(float* c, const uint32_t* a, const uint32_t* b) {
    asm volatile("mma.sync.aligned.m16n8k16.row.col.f32.f16.f16.f32 "
                 "{%0,%1,%2,%3}, {%4,%5,%6,%7}, {%8,%9}, {%0,%1,%2,%3};"
                 : "+f"(c[0]), "+f"(c[1]), "+f"(c[2]), "+f"(c[3])
                 : "r"(a[0]), "r"(a[1]), "r"(a[2]), "r"(a[3]), "r"(b[0]), "r"(b[1]));
}
/* exact scale by 2^-8 on packed half2 */
__device__ __forceinline__ uint32_t hscale8(uint32_t a) {
    __half2 v = *(__half2*)&a;
    __half2 s = __floats2half2_rn(0.00390625f, 0.00390625f);
    __half2 r = __hmul2(v, s);
    return *(uint32_t*)&r;
}

/* ------------------------------------------------------------------ */
/* Conversion kernels                                                  */
/* ------------------------------------------------------------------ */
__global__ __launch_bounds__(256) void to_f16(
    const float* __restrict__ in, __half* __restrict__ out, int n4)
{
    int i = blockIdx.x * blockDim.x + threadIdx.x;
    if (i >= n4) return;
    float4 v = ((const float4*)in)[i];
    __half2* op = (__half2*)out;
    op[2 * i + 0] = __floats2half2_rn(v.x, v.y);
    op[2 * i + 1] = __floats2half2_rn(v.z, v.w);
}

/* W [K][N] f32 -> Th (fp16) and Tls (fp16, (W-Th)*256), both [N][K] */
__global__ __launch_bounds__(256) void transpose_split_f16(
    const float* __restrict__ W, __half* __restrict__ Th,
    __half* __restrict__ Tls, int K, int N)
{
    __shared__ float tile[32][33];
    int n0 = blockIdx.x * 32, k0 = blockIdx.y * 32;
    int tx = threadIdx.x, ty = threadIdx.y;  /* 32 x 8 */
#pragma unroll
    for (int i = 0; i < 32; i += 8)
        tile[ty + i][tx] = W[(size_t)(k0 + ty + i) * N + n0 + tx];
    __syncthreads();
#pragma unroll
    for (int i = 0; i < 32; i += 8) {
        float v = tile[tx][ty + i];
        __half h = __float2half_rn(v);
        float r = (v - __half2float(h)) * 256.0f;
        Th[(size_t)(n0 + ty + i) * K + k0 + tx] = h;
        Tls[(size_t)(n0 + ty + i) * K + k0 + tx] = __float2half_rn(r);
    }
}

/* ------------------------------------------------------------------ */
/* fp16 2-term GEMM via mma.sync: C = A*B + bias                       */
/*   C = Ah*Bh + (Ah*2^-8)*((B-Bh)*2^8)                                */
/* A [M][K] fp16, Bh/Bls [N][K] fp16 (K-major)                         */
/* CTA 128x128, BK=32, 8 warps each 64x32                              */
/* 3-stage cp.async pipeline, 2 CTAs/SM                                */
/* ------------------------------------------------------------------ */
#define BKC 32
#define ROWP 40                                   /* padded row, f16 elems */
#define MAT_BYTES (128 * ROWP * 2)                /* 10240 */
#define AH_OFF 0
#define BH_OFF MAT_BYTES
#define BL_OFF (2 * MAT_BYTES)
#define STAGE_BYTES (3 * MAT_BYTES)               /* 30720 */
#define NSTAGES 3
#define GEMM_SMEM_BYTES (NSTAGES * STAGE_BYTES)   /* 92160 */

__global__ __launch_bounds__(256, 2) void gemm_mma(
    const __half* __restrict__ Ah,
    const __half* __restrict__ Bth, const __half* __restrict__ Btl,
    const float* __restrict__ bias, float* __restrict__ C, int N, int K)
{
    extern __shared__ char smem[];
    const uint32_t smem_base = smem_u32(smem);
    const int tid = threadIdx.x;
    const int warp = tid >> 5;
    const int lane = tid & 31;
    const int wm = warp >> 2;          /* 0..1  -> M offset 64*wm */
    const int wn = warp & 3;           /* 0..3  -> N offset 32*wn */
    const int rowBase = blockIdx.y * 128;
    const int colBase = blockIdx.x * 128;

    /* ldmatrix per-lane byte offsets (stage/kk-independent) */
    const int r8 = lane & 7;
    const int blk = lane >> 3;
    uint32_t offA[4], offB[2];
#pragma unroll
    for (int mt = 0; mt < 4; mt++) {
        int mrow = wm * 64 + mt * 16 + r8 + (blk & 1) * 8;
        offA[mt] = (uint32_t)((mrow * ROWP + (blk >> 1) * 8) * 2);
    }
#pragma unroll
    for (int p = 0; p < 2; p++) {
        int nrow = wn * 32 + p * 16 + (blk >> 1) * 8 + r8;
        offB[p] = (uint32_t)((nrow * ROWP + (blk & 1) * 8) * 2);
    }

    float acc[4][4][4];
#pragma unroll
    for (int mt = 0; mt < 4; mt++)
#pragma unroll
        for (int nt = 0; nt < 4; nt++)
#pragma unroll
            for (int i = 0; i < 4; i++) acc[mt][nt][i] = 0.0f;

    const int NS = K / BKC;

    /* producer: load chunk s into stage s%3 (3 matrices) */
#define LOAD_CHUNK(s) do {                                                     \
        int _st = (s) % NSTAGES; int _k0 = (s) * BKC;                          \
        uint32_t _sb = smem_base + _st * STAGE_BYTES;                          \
        _Pragma("unroll")                                                      \
        for (int _i = 0; _i < 2; _i++) {                                       \
            int _v = tid + (_i << 8);                                          \
            int _row = _v >> 2, _c8 = (_v & 3) << 3;                           \
            uint32_t _so = (uint32_t)(_row * ROWP + _c8) * 2;                  \
            size_t _ga = (size_t)(rowBase + _row) * K + _k0 + _c8;             \
            size_t _gb = (size_t)(colBase + _row) * K + _k0 + _c8;             \
            cpa16(_sb + AH_OFF + _so, Ah + _ga);                               \
            cpa16(_sb + BH_OFF + _so, Bth + _gb);                              \
            cpa16(_sb + BL_OFF + _so, Btl + _gb);                              \
        }                                                                      \
        cpa_commit();                                                          \
    } while (0)

    LOAD_CHUNK(0);
    LOAD_CHUNK(1);

    for (int s = 0; s < NS; s++) {
        /* chunk s ready when at most 1 newer group outstanding */
        if (s + 1 < NS) cpa_wait1(); else cpa_wait0();
        __syncthreads();
        if (s + 2 < NS) LOAD_CHUNK(s + 2);

        const uint32_t sb = smem_base + (s % NSTAGES) * STAGE_BYTES;
#pragma unroll
        for (int kk = 0; kk < BKC; kk += 16) {
            uint32_t ahf[4][4], asf[4][4], bhf[2][4], blf[2][4];
#pragma unroll
            for (int mt = 0; mt < 4; mt++)
                ldm4(ahf[mt], sb + AH_OFF + offA[mt] + kk * 2);
#pragma unroll
            for (int p = 0; p < 2; p++) {
                ldm4(bhf[p], sb + BH_OFF + offB[p] + kk * 2);
                ldm4(blf[p], sb + BL_OFF + offB[p] + kk * 2);
            }
#pragma unroll
            for (int mt = 0; mt < 4; mt++)
#pragma unroll
                for (int i = 0; i < 4; i++)
                    asf[mt][i] = hscale8(ahf[mt][i]);
#pragma unroll
            for (int mt = 0; mt < 4; mt++)
#pragma unroll
                for (int nt = 0; nt < 4; nt++) {
                    const uint32_t* bh = &bhf[nt >> 1][(nt & 1) * 2];
                    const uint32_t* bl = &blf[nt >> 1][(nt & 1) * 2];
                    mma16816h(acc[mt][nt], ahf[mt], bh);
                    mma16816h(acc[mt][nt], asf[mt], bl);
                }
        }
        __syncthreads();
    }

    /* epilogue */
#pragma unroll
    for (int mt = 0; mt < 4; mt++) {
        int row0 = rowBase + wm * 64 + mt * 16 + (lane >> 2);
#pragma unroll
        for (int nt = 0; nt < 4; nt++) {
            int col = colBase + wn * 32 + nt * 8 + (lane & 3) * 2;
            float b0 = bias[col], b1 = bias[col + 1];
            float2 v0 = make_float2(acc[mt][nt][0] + b0, acc[mt][nt][1] + b1);
            float2 v1 = make_float2(acc[mt][nt][2] + b0, acc[mt][nt][3] + b1);
            *(float2*)(C + (size_t)row0 * N + col) = v0;
            *(float2*)(C + (size_t)(row0 + 8) * N + col) = v1;
        }
    }
#undef LOAD_CHUNK
}

/* ------------------------------------------------------------------ */
/* Causal flash attention, fp32 (unchanged, known-correct)             */
/* ------------------------------------------------------------------ */
#define QTILE 64
#define KTILE 64
#define NQT (Tv / QTILE)
#define QK_STRIDE 129
#define V_STRIDE 132
#define P_STRIDE 68
#define FLASH_SMEM_FLOATS (64 * QK_STRIDE * 2 + 64 * V_STRIDE + 64 * P_STRIDE + 3 * 64)
#define FLASH_SMEM_BYTES (FLASH_SMEM_FLOATS * 4)

__global__ __launch_bounds__(256) void flash_attn(
    const float* __restrict__ qkv, float* __restrict__ Y)
{
    extern __shared__ float sm[];
    float* Qs = sm;
    float* Ks = Qs + 64 * QK_STRIDE;
    float* Vs = Ks + 64 * QK_STRIDE;
    float* Ps = Vs + 64 * V_STRIDE;
    float* mrow = Ps + 64 * P_STRIDE;
    float* lrow = mrow + 64;
    float* frow = lrow + 64;

    const int t = threadIdx.x;
    const int blk = blockIdx.x;
    const int qt = blk % NQT;
    const int h = (blk / NQT) % NH;
    const int b = blk / (NQT * NH);

    const size_t rowStride = 3 * Cv;
    const float scale = 0.08838834764831845f;

    const int s_r0 = (t / 16) * 4;
    const int s_c0 = (t % 16) * 4;
    const int o_r0 = (t / 16) * 4;
    const int o_c0 = (t % 16) * 8;
    const int rRow = t >> 2;
    const int seg = t & 3;

    const float* qbase = qkv + ((size_t)b * Tv + qt * QTILE) * rowStride + h * HD;
#pragma unroll
    for (int chunk = 0; chunk < 8; chunk++) {
        int linear = chunk * 1024 + t * 4;
        int r = linear >> 7;
        int d = linear & 127;
        float4 v = *(const float4*)(qbase + (size_t)r * rowStride + d);
        Qs[r * QK_STRIDE + d + 0] = v.x;
        Qs[r * QK_STRIDE + d + 1] = v.y;
        Qs[r * QK_STRIDE + d + 2] = v.z;
        Qs[r * QK_STRIDE + d + 3] = v.w;
    }
    if (t < 64) { mrow[t] = -3.0e38f; lrow[t] = 0.0f; }

    float acc[4][8];
#pragma unroll
    for (int i = 0; i < 4; i++)
#pragma unroll
        for (int j = 0; j < 8; j++) acc[i][j] = 0.0f;

    __syncthreads();

    for (int kt = 0; kt <= qt; kt++) {
        const float* kbase = qkv + ((size_t)b * Tv + kt * KTILE) * rowStride + Cv + h * HD;
        const float* vbase = kbase + Cv;
#pragma unroll
        for (int chunk = 0; chunk < 8; chunk++) {
            int linear = chunk * 1024 + t * 4;
            int r = linear >> 7;
            int d = linear & 127;
            float4 kv = *(const float4*)(kbase + (size_t)r * rowStride + d);
            Ks[r * QK_STRIDE + d + 0] = kv.x;
            Ks[r * QK_STRIDE + d + 1] = kv.y;
            Ks[r * QK_STRIDE + d + 2] = kv.z;
            Ks[r * QK_STRIDE + d + 3] = kv.w;
            float4 vv = *(const float4*)(vbase + (size_t)r * rowStride + d);
            *(float4*)&Vs[r * V_STRIDE + d] = vv;
        }
        __syncthreads();

        float sreg[4][4];
#pragma unroll
        for (int i = 0; i < 4; i++)
#pragma unroll
            for (int j = 0; j < 4; j++) sreg[i][j] = 0.0f;

#pragma unroll 4
        for (int k = 0; k < 128; k++) {
            float a[4], bb[4];
#pragma unroll
            for (int i = 0; i < 4; i++) a[i] = Qs[(s_r0 + i) * QK_STRIDE + k];
#pragma unroll
            for (int j = 0; j < 4; j++) bb[j] = Ks[(s_c0 + j) * QK_STRIDE + k];
#pragma unroll
            for (int i = 0; i < 4; i++)
#pragma unroll
                for (int j = 0; j < 4; j++)
                    sreg[i][j] += a[i] * bb[j];
        }

        const bool diag = (kt == qt);
#pragma unroll
        for (int i = 0; i < 4; i++) {
            float4 o;
            float v0 = sreg[i][0] * scale;
            float v1 = sreg[i][1] * scale;
            float v2 = sreg[i][2] * scale;
            float v3 = sreg[i][3] * scale;
            if (diag) {
                int qr = s_r0 + i;
                if (s_c0 + 0 > qr) v0 = -1.0e30f;
                if (s_c0 + 1 > qr) v1 = -1.0e30f;
                if (s_c0 + 2 > qr) v2 = -1.0e30f;
                if (s_c0 + 3 > qr) v3 = -1.0e30f;
            }
            o.x = v0; o.y = v1; o.z = v2; o.w = v3;
            *(float4*)&Ps[(s_r0 + i) * P_STRIDE + s_c0] = o;
        }
        __syncthreads();

        {
            float mOld = mrow[rRow];
            float lOld = lrow[rRow];
            float* prow = Ps + rRow * P_STRIDE + seg * 16;
            float lm = -3.0e38f;
#pragma unroll
            for (int c = 0; c < 16; c++) lm = fmaxf(lm, prow[c]);
            lm = fmaxf(lm, __shfl_xor_sync(0xffffffffu, lm, 1));
            lm = fmaxf(lm, __shfl_xor_sync(0xffffffffu, lm, 2));
            float mNew = fmaxf(mOld, lm);
            float lsum = 0.0f;
#pragma unroll
            for (int c = 0; c < 16; c++) {
                float p = __expf(prow[c] - mNew);
                prow[c] = p;
                lsum += p;
            }
            lsum += __shfl_xor_sync(0xffffffffu, lsum, 1);
            lsum += __shfl_xor_sync(0xffffffffu, lsum, 2);
            if (seg == 0) {
                float f = __expf(mOld - mNew);
                frow[rRow] = f;
                mrow[rRow] = mNew;
                lrow[rRow] = lOld * f + lsum;
            }
        }
        __syncthreads();

        {
            float f[4];
#pragma unroll
            for (int i = 0; i < 4; i++) f[i] = frow[o_r0 + i];
#pragma unroll
            for (int i = 0; i < 4; i++)
#pragma unroll
                for (int j = 0; j < 8; j++) acc[i][j] *= f[i];

#pragma unroll 2
            for (int n = 0; n < 64; n++) {
                float p[4];
#pragma unroll
                for (int i = 0; i < 4; i++) p[i] = Ps[(o_r0 + i) * P_STRIDE + n];
                float4 va = *(const float4*)&Vs[n * V_STRIDE + o_c0];
                float4 vb = *(const float4*)&Vs[n * V_STRIDE + o_c0 + 4];
#pragma unroll
                for (int i = 0; i < 4; i++) {
                    acc[i][0] += p[i] * va.x;
                    acc[i][1] += p[i] * va.y;
                    acc[i][2] += p[i] * va.z;
                    acc[i][3] += p[i] * va.w;
                    acc[i][4] += p[i] * vb.x;
                    acc[i][5] += p[i] * vb.y;
                    acc[i][6] += p[i] * vb.z;
                    acc[i][7] += p[i] * vb.w;
                }
            }
        }
        __syncthreads();
    }

    float* ybase = Y + ((size_t)b * Tv + qt * QTILE) * Cv + h * HD;
#pragma unroll
    for (int i = 0; i < 4; i++) {
        float inv = 1.0f / lrow[o_r0 + i];
        float4 o1, o2;
        o1.x = acc[i][0] * inv; o1.y = acc[i][1] * inv;
        o1.z = acc[i][2] * inv; o1.w = acc[i][3] * inv;
        o2.x = acc[i][4] * inv; o2.y = acc[i][5] * inv;
        o2.z = acc[i][6] * inv; o2.w = acc[i][7] * inv;
        *(float4*)(ybase + (size_t)(o_r0 + i) * Cv + o_c0) = o1;
        *(float4*)(ybase + (size_t)(o_r0 + i) * Cv + o_c0 + 4) = o2;
    }
}

/* ------------------------------------------------------------------ */
extern "C" void kernel_launch(void* const* d_in, const int* in_sizes, int n_in,
                              void* d_out, int out_size)
{
    (void)in_sizes; (void)n_in; (void)out_size;
    const float* x      = (const float*)d_in[0];
    const float* W_attn = (const float*)d_in[1];
    const float* b_attn = (const float*)d_in[2];
    const float* W_proj = (const float*)d_in[3];
    const float* b_proj = (const float*)d_in[4];
    float* out = (float*)d_out;

    float *qkv, *y;
    __half *xh, *yh, *wah, *wal, *wph, *wpl;
    cudaGetSymbolAddress((void**)&qkv, g_qkv);
    cudaGetSymbolAddress((void**)&y, g_y);
    cudaGetSymbolAddress((void**)&xh, g_xh);
    cudaGetSymbolAddress((void**)&yh, g_yh);
    cudaGetSymbolAddress((void**)&wah, g_wah);
    cudaGetSymbolAddress((void**)&wal, g_wal);
    cudaGetSymbolAddress((void**)&wph, g_wph);
    cudaGetSymbolAddress((void**)&wpl, g_wpl);

    cudaFuncSetAttribute(gemm_mma, cudaFuncAttributeMaxDynamicSharedMemorySize, GEMM_SMEM_BYTES);
    cudaFuncSetAttribute(flash_attn, cudaFuncAttributeMaxDynamicSharedMemorySize, FLASH_SMEM_BYTES);

    const int n4x = (M_ROWS * Cv) / 4;
    to_f16<<<(n4x + 255) / 256, 256>>>(x, xh, n4x);
    transpose_split_f16<<<dim3(N_QKV / 32, Cv / 32), dim3(32, 8)>>>(W_attn, wah, wal, Cv, N_QKV);
    transpose_split_f16<<<dim3(Cv / 32, Cv / 32), dim3(32, 8)>>>(W_proj, wph, wpl, Cv, Cv);

    gemm_mma<<<dim3(N_QKV / 128, M_ROWS / 128), 256, GEMM_SMEM_BYTES>>>(
        xh, wah, wal, b_attn, qkv, N_QKV, Cv);

    flash_attn<<<dim3(Bv * NH * NQT), 256, FLASH_SMEM_BYTES>>>(qkv, y);

    to_f16<<<(n4x + 255) / 256, 256>>>(y, yh, n4x);
    gemm_mma<<<dim3(Cv / 128, M_ROWS / 128), 256, GEMM_SMEM_BYTES>>>(
        yh, wph, wpl, b_proj, out, Cv, Cv);
}